// round 9
// baseline (speedup 1.0000x reference)
#include <cuda_runtime.h>
#include <cuda_fp16.h>
#include <cuda_bf16.h>

#define B_  16
#define LQ  256
#define LK  256
#define QD  256
#define HD  128
#define VD  128
#define KT  8     // k-rows per CTA; 8 warps: warp w -> qhalf w>>2, k-rows {2(w&3), 2(w&3)+1}

// f16 projected q/k, TRANSPOSED per batch: [b][h][q] / [b][h][k]
__device__ __half g_qpT[B_ * HD * LQ];
__device__ __half g_kpT[B_ * HD * LK];

namespace {  // internal linkage: immune to cuda_fp16.hpp name collisions

__device__ __forceinline__ __half2 tanh_h2_(__half2 x) {
    unsigned xo, xi = *(unsigned*)&x;
    asm("tanh.approx.f16x2 %0, %1;" : "=r"(xo) : "r"(xi));
    return *(__half2*)&xo;
}
__device__ __forceinline__ unsigned long long pk2_(float lo, float hi) {
    unsigned long long r;
    asm("mov.b64 %0, {%1, %2};" : "=l"(r) : "f"(lo), "f"(hi));
    return r;
}
__device__ __forceinline__ void upk2_(unsigned long long v, float& lo, float& hi) {
    asm("mov.b64 {%0, %1}, %2;" : "=f"(lo), "=f"(hi) : "l"(v));
}
__device__ __forceinline__ void fma2_(unsigned long long& d, unsigned long long a,
                                      unsigned long long b) {
    asm("fma.rn.f32x2 %0, %1, %2, %0;" : "+l"(d) : "l"(a), "l"(b));
}

}  // namespace

// ============================================================================
// Kernel 1: qp = query @ Wq, kp = key @ Wk  (fp32 math, f32x2 FFMA, epilogue
// stores f16 TRANSPOSED [b][h][row]). BM=32, BN=128, BK=32, 256 threads,
// thread tile 4 rows x 4 cols. grid (128,2) = 256 CTAs (was 128 -> SMs idle).
// ============================================================================
__global__ __launch_bounds__(256) void proj_kernel(
    const float* __restrict__ q_in, const float* __restrict__ k_in,
    const float* __restrict__ Wq,   const float* __restrict__ Wk)
{
    const float* X  = blockIdx.y ? k_in : q_in;
    const float* W  = blockIdx.y ? Wk : Wq;
    __half*      YT = blockIdx.y ? g_kpT : g_qpT;

    __shared__ __align__(16) float As[32][36];   // [k][row], stride 144B (16B mult)
    __shared__ __align__(16) float Bs[32][128];  // [k][h]

    const int t  = threadIdx.x;
    const int tx = t & 31;          // col group (4 h)
    const int ty = t >> 5;          // row group (4 rows), 0..7
    const int r0 = blockIdx.x * 32;

    unsigned long long acc[2][4];   // [rowpair][col]
    #pragma unroll
    for (int rp = 0; rp < 2; rp++)
        #pragma unroll
        for (int c = 0; c < 4; c++) acc[rp][c] = 0ull;

    for (int kb = 0; kb < QD; kb += 32) {
        __syncthreads();
        {   // A tile 32x32 transposed: one float4 per thread
            int kk4 = t & 7, r = t >> 3;
            float4 a4 = *(const float4*)&X[(r0 + r) * QD + kb + kk4 * 4];
            As[kk4 * 4 + 0][r] = a4.x;
            As[kk4 * 4 + 1][r] = a4.y;
            As[kk4 * 4 + 2][r] = a4.z;
            As[kk4 * 4 + 3][r] = a4.w;
        }
        {   // B tile 32x128: 4 float4 per thread
            int h4 = t & 31, kk = t >> 5;
            #pragma unroll
            for (int j = 0; j < 4; j++)
                *(float4*)&Bs[kk + 8 * j][h4 * 4] =
                    *(const float4*)&W[(kb + kk + 8 * j) * HD + h4 * 4];
        }
        __syncthreads();
        #pragma unroll
        for (int kk = 0; kk < 32; kk++) {
            float4 a  = *(const float4*)&As[kk][ty * 4];   // bcast
            float4 bv = *(const float4*)&Bs[kk][tx * 4];   // lane-strided
            unsigned long long ap0 = pk2_(a.x, a.y);
            unsigned long long ap1 = pk2_(a.z, a.w);
            unsigned long long bb[4] = { pk2_(bv.x, bv.x), pk2_(bv.y, bv.y),
                                         pk2_(bv.z, bv.z), pk2_(bv.w, bv.w) };
            #pragma unroll
            for (int c = 0; c < 4; c++) { fma2_(acc[0][c], ap0, bb[c]);
                                          fma2_(acc[1][c], ap1, bb[c]); }
        }
    }

    // Epilogue: per col c (=h), 4 rows -> 2 half2 -> one STG.64
    const int bb   = r0 / LQ;
    const int qloc = (r0 % LQ) + ty * 4;
    #pragma unroll
    for (int c = 0; c < 4; c++) {
        int h = tx * 4 + c;
        float r01lo, r01hi, r23lo, r23hi;
        upk2_(acc[0][c], r01lo, r01hi);
        upk2_(acc[1][c], r23lo, r23hi);
        __half2 p0 = __floats2half2_rn(r01lo, r01hi);
        __half2 p1 = __floats2half2_rn(r23lo, r23hi);
        uint2 out = make_uint2(*(unsigned*)&p0, *(unsigned*)&p1);
        *(uint2*)&YT[(bb * HD + h) * LQ + qloc] = out;
    }
}

// ============================================================================
// Kernel 2: scores (f16x2 MUFU) + softmax(over q) + context.
// grid = 512 CTAs, 256 threads (8 warps) -> occ ~43%.
// Warp w: qhalf = w>>2 (128 q's), k-rows {2(w&3), 2(w&3)+1}, lane = q pair.
// Per h per warp: LDS.32 qp(half2) + LDS.128 bcast {kp0d,kp1d,vd} ->
//   2 HADD2 + 2 tanh.f16x2 + 2 HFMA2 (4 indep chains, flush to f32 every 8 h).
// smem 40KB union: [qps 64hx128u (32K) | kvs 64x4 uint4 (4K)]
//               <-> [S 8x256 f32 (8K) | val_s 64x128 f32 (32K)]
// ============================================================================
__global__ __launch_bounds__(256) void attn_kernel(
    const float* __restrict__ value, const float* __restrict__ vvec,
    float* __restrict__ ctx, float* __restrict__ attn)
{
    const int b  = blockIdx.x >> 5;          // 32 k-tiles per batch
    const int k0 = (blockIdx.x & 31) * KT;

    __shared__ __align__(16) float sm[10240];          // 40960 B union
    unsigned* qps   = (unsigned*)sm;                    // [64][128] half2  (32KB)
    uint4*    kvs   = (uint4*)((char*)sm + 32768);      // [64][4]          (4KB)
    float*    S     = sm;                               // [8][256]         (8KB)
    float*    val_s = sm + 2048;                        // [64][128]        (32KB)

    const int t    = threadIdx.x;
    const int w    = t >> 5;
    const int lane = t & 31;
    const int qh   = w >> 2;        // q half: 0 or 1
    const int wk   = w & 3;         // k-row pair index

    const __half* kpT = g_kpT + (size_t)b * HD * LK;
    const __half* qpT = g_qpT + (size_t)b * HD * LQ;

    float accf[2][2][2];            // [q-pass][k][q]
    #pragma unroll
    for (int p = 0; p < 2; p++)
        #pragma unroll
        for (int kk = 0; kk < 2; kk++) { accf[p][kk][0] = 0.f; accf[p][kk][1] = 0.f; }

    // ---- Phase B: scores ----
    #pragma unroll
    for (int hh = 0; hh < 2; hh++) {
        __syncthreads();            // prior readers of qps/kvs done
        {   // kvs[h][ww] = {dup(kp[2ww]), dup(kp[2ww+1]), dup(v), 0}; 256 entries
            int h = t >> 2, ww = t & 3;
            __half2 kk2 = *(const __half2*)&kpT[(hh * 64 + h) * LK + k0 + 2 * ww];
            __half2 vd  = __float2half2_rn(vvec[hh * 64 + h]);
            __half2 k0d = __low2half2(kk2), k1d = __high2half2(kk2);
            kvs[t] = make_uint4(*(unsigned*)&k0d, *(unsigned*)&k1d,
                                *(unsigned*)&vd, 0u);
        }
        {   // qps: full 64h x 256q tile, 2048 uint4, 8 per thread
            #pragma unroll
            for (int j = 0; j < 8; j++) {
                int idx = t + 256 * j;
                int h = idx >> 5, u4 = idx & 31;
                ((uint4*)qps)[h * 32 + u4] =
                    *(const uint4*)&qpT[(hh * 64 + h) * LQ + u4 * 8];
            }
        }
        __syncthreads();
        #pragma unroll
        for (int p = 0; p < 2; p++) {
            const int qidx = qh * 64 + p * 32 + lane;   // uint index in 128-uint row
            #pragma unroll
            for (int h8 = 0; h8 < 64; h8 += 8) {
                __half2 a00 = __float2half2_rn(0.f), a01 = a00;
                __half2 a10 = a00, a11 = a00;
                #pragma unroll
                for (int j = 0; j < 8; j++) {
                    int h = h8 + j;
                    unsigned qu = qps[h * 128 + qidx];
                    uint4 kv = kvs[h * 4 + wk];                 // bcast
                    __half2 qv  = *(__half2*)&qu;
                    __half2 kp0 = *(__half2*)&kv.x;
                    __half2 kp1 = *(__half2*)&kv.y;
                    __half2 vd  = *(__half2*)&kv.z;
                    __half2 t0 = tanh_h2_(__hadd2(qv, kp0));
                    __half2 t1 = tanh_h2_(__hadd2(qv, kp1));
                    if (j & 1) { a01 = __hfma2(t0, vd, a01);
                                 a11 = __hfma2(t1, vd, a11); }
                    else       { a00 = __hfma2(t0, vd, a00);
                                 a10 = __hfma2(t1, vd, a10); }
                }
                accf[p][0][0] += __low2float(a00)  + __low2float(a01);
                accf[p][0][1] += __high2float(a00) + __high2float(a01);
                accf[p][1][0] += __low2float(a10)  + __low2float(a11);
                accf[p][1][1] += __high2float(a10) + __high2float(a11);
            }
        }
    }

    // ---- Phase C: softmax over q ----
    __syncthreads();                // phase-B smem reads done before S overlay
    #pragma unroll
    for (int kk = 0; kk < 2; kk++) {
        int krow = 2 * wk + kk;
        #pragma unroll
        for (int p = 0; p < 2; p++)
            *(float2*)&S[krow * 256 + qh * 128 + p * 64 + 2 * lane] =
                make_float2(accf[p][kk][0], accf[p][kk][1]);
    }
    __syncthreads();                // scores complete; warp w reduces row w
    {
        float vals[8], m = -1e30f;
        #pragma unroll
        for (int i = 0; i < 8; i++) {
            vals[i] = S[w * 256 + lane + 32 * i];
            m = fmaxf(m, vals[i]);
        }
        #pragma unroll
        for (int o = 16; o > 0; o >>= 1)
            m = fmaxf(m, __shfl_xor_sync(0xffffffffu, m, o));
        float s = 0.f;
        #pragma unroll
        for (int i = 0; i < 8; i++) { vals[i] = __expf(vals[i] - m); s += vals[i]; }
        #pragma unroll
        for (int o = 16; o > 0; o >>= 1)
            s += __shfl_xor_sync(0xffffffffu, s, o);
        float inv = 1.0f / s;
        #pragma unroll
        for (int i = 0; i < 8; i++)
            S[w * 256 + lane + 32 * i] = vals[i] * inv;
        __syncwarp();
        float* arow = attn + (size_t)(b * LK + k0 + w) * LQ;
        #pragma unroll
        for (int j = 0; j < 2; j++)
            *(float4*)&arow[lane * 4 + 128 * j] =
                *(const float4*)&S[w * 256 + lane * 4 + 128 * j];
    }

    // ---- Phase D: ctx[k][vd] = sum_q P[k][q] * value[b][q][vd]; warp w = row w ----
    float4 c = make_float4(0.f, 0.f, 0.f, 0.f);
    const float* val_b = value + (size_t)b * LQ * VD;
    for (int qt = 0; qt < 4; qt++) {
        __syncthreads();
        #pragma unroll
        for (int j = 0; j < 8; j++) {      // stage 64x128 value tile (2048 float4)
            int idx = t + 256 * j;
            int q = idx >> 5, c4 = idx & 31;
            *(float4*)&val_s[q * VD + c4 * 4] =
                *(const float4*)&val_b[(qt * 64 + q) * VD + c4 * 4];
        }
        __syncthreads();
        #pragma unroll
        for (int q4 = 0; q4 < 16; q4++) {  // 4 q per step
            float4 P = *(const float4*)&S[w * 256 + qt * 64 + q4 * 4];  // bcast
            const float pa[4] = { P.x, P.y, P.z, P.w };
            #pragma unroll
            for (int u = 0; u < 4; u++) {
                float4 vv = *(const float4*)&val_s[(q4 * 4 + u) * VD + lane * 4];
                c.x += pa[u] * vv.x; c.y += pa[u] * vv.y;
                c.z += pa[u] * vv.z; c.w += pa[u] * vv.w;
            }
        }
    }
    *(float4*)&ctx[(size_t)(b * LK + k0 + w) * VD + lane * 4] = c;
}

// ============================================================================
// Launch: inputs: query, key, value, Wq, Wk, v
// d_out = context [B,LK,VD] followed by attention [B,LK,LQ]
// ============================================================================
extern "C" void kernel_launch(void* const* d_in, const int* in_sizes, int n_in,
                              void* d_out, int out_size)
{
    const float* query = (const float*)d_in[0];
    const float* key_t = (const float*)d_in[1];
    const float* value = (const float*)d_in[2];
    const float* Wq    = (const float*)d_in[3];
    const float* Wk    = (const float*)d_in[4];
    const float* vvec  = (const float*)d_in[5];

    float* ctx  = (float*)d_out;
    float* attn = ctx + (size_t)B_ * LK * VD;

    dim3 g1((B_ * LQ) / 32, 2);          // 128 x 2 = 256 CTAs
    proj_kernel<<<g1, 256>>>(query, key_t, Wq, Wk);
    attn_kernel<<<B_ * (LK / KT), 256>>>(value, vvec, ctx, attn);
}

// round 10
// speedup vs baseline: 1.2709x; 1.2709x over previous
#include <cuda_runtime.h>
#include <cuda_fp16.h>
#include <cuda_bf16.h>

#define B_  16
#define LQ  256
#define LK  256
#define QD  256
#define HD  128
#define VD  128
#define KT  4     // k-rows per CTA; 4 warps, warp w owns k-row w

// f16 projected q/k, TRANSPOSED per batch: [b][h][q] / [b][h][k]
__device__ __half g_qpT[B_ * HD * LQ];
__device__ __half g_kpT[B_ * HD * LK];

namespace {  // internal linkage: immune to cuda_fp16.hpp name collisions

__device__ __forceinline__ __half2 tanh_h2_(__half2 x) {
    unsigned xo, xi = *(unsigned*)&x;
    asm("tanh.approx.f16x2 %0, %1;" : "=r"(xo) : "r"(xi));
    return *(__half2*)&xo;
}
__device__ __forceinline__ unsigned long long pk2_(float lo, float hi) {
    unsigned long long r;
    asm("mov.b64 %0, {%1, %2};" : "=l"(r) : "f"(lo), "f"(hi));
    return r;
}
__device__ __forceinline__ void upk2_(unsigned long long v, float& lo, float& hi) {
    asm("mov.b64 {%0, %1}, %2;" : "=f"(lo), "=f"(hi) : "l"(v));
}
__device__ __forceinline__ void fma2_(unsigned long long& d, unsigned long long a,
                                      unsigned long long b) {
    asm("fma.rn.f32x2 %0, %1, %2, %0;" : "+l"(d) : "l"(a), "l"(b));
}

}  // namespace

// ============================================================================
// Kernel 1: qp = query @ Wq, kp = key @ Wk  (fp32 math, f32x2 FFMA, epilogue
// stores f16 TRANSPOSED [b][h][row]). BM=32, BN=128, BK=32, 256 threads,
// thread tile 4 rows x 4 cols. grid (128,2) = 256 CTAs.
// ============================================================================
__global__ __launch_bounds__(256) void proj_kernel(
    const float* __restrict__ q_in, const float* __restrict__ k_in,
    const float* __restrict__ Wq,   const float* __restrict__ Wk)
{
    const float* X  = blockIdx.y ? k_in : q_in;
    const float* W  = blockIdx.y ? Wk : Wq;
    __half*      YT = blockIdx.y ? g_kpT : g_qpT;

    __shared__ __align__(16) float As[32][36];
    __shared__ __align__(16) float Bs[32][128];

    const int t  = threadIdx.x;
    const int tx = t & 31;
    const int ty = t >> 5;
    const int r0 = blockIdx.x * 32;

    unsigned long long acc[2][4];
    #pragma unroll
    for (int rp = 0; rp < 2; rp++)
        #pragma unroll
        for (int c = 0; c < 4; c++) acc[rp][c] = 0ull;

    for (int kb = 0; kb < QD; kb += 32) {
        __syncthreads();
        {   // A tile 32x32 transposed
            int kk4 = t & 7, r = t >> 3;
            float4 a4 = *(const float4*)&X[(r0 + r) * QD + kb + kk4 * 4];
            As[kk4 * 4 + 0][r] = a4.x;
            As[kk4 * 4 + 1][r] = a4.y;
            As[kk4 * 4 + 2][r] = a4.z;
            As[kk4 * 4 + 3][r] = a4.w;
        }
        {   // B tile 32x128
            int h4 = t & 31, kk = t >> 5;
            #pragma unroll
            for (int j = 0; j < 4; j++)
                *(float4*)&Bs[kk + 8 * j][h4 * 4] =
                    *(const float4*)&W[(kb + kk + 8 * j) * HD + h4 * 4];
        }
        __syncthreads();
        #pragma unroll
        for (int kk = 0; kk < 32; kk++) {
            float4 a  = *(const float4*)&As[kk][ty * 4];
            float4 bv = *(const float4*)&Bs[kk][tx * 4];
            unsigned long long ap0 = pk2_(a.x, a.y);
            unsigned long long ap1 = pk2_(a.z, a.w);
            unsigned long long bb[4] = { pk2_(bv.x, bv.x), pk2_(bv.y, bv.y),
                                         pk2_(bv.z, bv.z), pk2_(bv.w, bv.w) };
            #pragma unroll
            for (int c = 0; c < 4; c++) { fma2_(acc[0][c], ap0, bb[c]);
                                          fma2_(acc[1][c], ap1, bb[c]); }
        }
    }

    const int bb   = r0 / LQ;
    const int qloc = (r0 % LQ) + ty * 4;
    #pragma unroll
    for (int c = 0; c < 4; c++) {
        int h = tx * 4 + c;
        float r01lo, r01hi, r23lo, r23hi;
        upk2_(acc[0][c], r01lo, r01hi);
        upk2_(acc[1][c], r23lo, r23hi);
        __half2 p0 = __floats2half2_rn(r01lo, r01hi);
        __half2 p1 = __floats2half2_rn(r23lo, r23hi);
        uint2 out = make_uint2(*(unsigned*)&p0, *(unsigned*)&p1);
        *(uint2*)&YT[(bb * HD + h) * LQ + qloc] = out;
    }
}

// ============================================================================
// Kernel 2: scores (f16x2 MUFU) + warp-local softmax + context.
// grid = B*(LK/4) = 1024 CTAs, 128 threads (4 warps) -> ~6.9 CTAs/SM, occ ~42%.
// Warp w owns k-row w; lane owns q's {4*lane..4*lane+3} (2 half2); 2 q-passes.
// Per h: LDS.64 qp (2wf) + LDS.64 bcast {kp dup, v dup} (1wf) ->
//        2 HADD2 + 2 tanh.f16x2 + 2 HFMA2  (4 indep chains, f32 flush per 8 h).
// smem 20.5KB union: [qps 64x68u (17.4K) | kvs 64x4 uint2 (2K)]
//                <-> [S 4x256 f32 (4K) | val_s 32x128 f32 (16K)]
// ============================================================================
__global__ __launch_bounds__(128, 6) void attn_kernel(
    const float* __restrict__ value, const float* __restrict__ vvec,
    float* __restrict__ ctx, float* __restrict__ attn)
{
    const int b  = blockIdx.x >> 6;          // 64 k-tiles per batch
    const int k0 = (blockIdx.x & 63) * KT;

    __shared__ __align__(16) float sm[5120];           // 20480 B union
    unsigned* qps   = (unsigned*)sm;                    // [64][68] half2 (17408 B)
    uint2*    kvs   = (uint2*)((char*)sm + 17408);      // [64][4]        (2048 B)
    float*    S     = sm;                               // [4][256]       (4096 B)
    float*    val_s = sm + 1024;                        // [32][128]      (16384 B)

    const int t    = threadIdx.x;
    const int w    = t >> 5;
    const int lane = t & 31;

    const __half* kpT = g_kpT + (size_t)b * HD * LK;
    const __half* qpT = g_qpT + (size_t)b * HD * LQ;

    float accf[2][4];                // [q-pass][4 q]
    #pragma unroll
    for (int p = 0; p < 2; p++)
        #pragma unroll
        for (int i = 0; i < 4; i++) accf[p][i] = 0.f;

    // ---- Phase B: scores ----
    #pragma unroll
    for (int hh = 0; hh < 2; hh++) {
        #pragma unroll
        for (int p = 0; p < 2; p++) {
            __syncthreads();         // prior pass's qps/kvs readers done
            if (p == 0) {            // kvs[h][ww] = {dup(kp[k0+ww]), dup(v)}
                #pragma unroll
                for (int j = 0; j < 2; j++) {
                    int idx = t + 128 * j;
                    int h = idx >> 2, ww = idx & 3;
                    __half  kp = kpT[(hh * 64 + h) * LK + k0 + ww];
                    __half2 kd = __half2half2(kp);
                    __half2 vd = __float2half2_rn(vvec[hh * 64 + h]);
                    kvs[idx] = make_uint2(*(unsigned*)&kd, *(unsigned*)&vd);
                }
            }
            // qps: 64h x 128q (this pass) = 1024 uint4, 8 per thread
            #pragma unroll
            for (int j = 0; j < 8; j++) {
                int idx = t + 128 * j;
                int h = idx >> 4, u4 = idx & 15;
                ((uint4*)(qps + h * 68))[u4] =
                    *(const uint4*)&qpT[(hh * 64 + h) * LQ + p * 128 + u4 * 8];
            }
            __syncthreads();
            #pragma unroll
            for (int h8 = 0; h8 < 64; h8 += 8) {
                __half2 a0e = __float2half2_rn(0.f), a0o = a0e;
                __half2 a1e = a0e, a1o = a0e;
                #pragma unroll
                for (int j = 0; j < 8; j++) {
                    int h = h8 + j;
                    uint2 qu = *(const uint2*)&qps[h * 68 + 2 * lane];
                    uint2 kv = kvs[h * 4 + w];                  // bcast
                    __half2 qv0 = *(__half2*)&qu.x;
                    __half2 qv1 = *(__half2*)&qu.y;
                    __half2 kpd = *(__half2*)&kv.x;
                    __half2 vd  = *(__half2*)&kv.y;
                    __half2 t0 = tanh_h2_(__hadd2(qv0, kpd));
                    __half2 t1 = tanh_h2_(__hadd2(qv1, kpd));
                    if (j & 1) { a0o = __hfma2(t0, vd, a0o);
                                 a1o = __hfma2(t1, vd, a1o); }
                    else       { a0e = __hfma2(t0, vd, a0e);
                                 a1e = __hfma2(t1, vd, a1e); }
                }
                accf[p][0] += __low2float(a0e)  + __low2float(a0o);
                accf[p][1] += __high2float(a0e) + __high2float(a0o);
                accf[p][2] += __low2float(a1e)  + __low2float(a1o);
                accf[p][3] += __high2float(a1e) + __high2float(a1o);
            }
        }
    }

    // ---- Phase C: warp-local softmax over q (warp w = k-row w) ----
    __syncthreads();                 // phase-B smem reads done before S overlay
    {
        float m = -1e30f;
        #pragma unroll
        for (int p = 0; p < 2; p++)
            #pragma unroll
            for (int i = 0; i < 4; i++) m = fmaxf(m, accf[p][i]);
        #pragma unroll
        for (int o = 16; o > 0; o >>= 1)
            m = fmaxf(m, __shfl_xor_sync(0xffffffffu, m, o));
        float s = 0.f;
        #pragma unroll
        for (int p = 0; p < 2; p++)
            #pragma unroll
            for (int i = 0; i < 4; i++) {
                accf[p][i] = __expf(accf[p][i] - m);
                s += accf[p][i];
            }
        #pragma unroll
        for (int o = 16; o > 0; o >>= 1)
            s += __shfl_xor_sync(0xffffffffu, s, o);
        float inv = 1.0f / s;
        float* arow = attn + (size_t)(b * LK + k0 + w) * LQ;
        #pragma unroll
        for (int p = 0; p < 2; p++) {
            float4 pr = make_float4(accf[p][0] * inv, accf[p][1] * inv,
                                    accf[p][2] * inv, accf[p][3] * inv);
            *(float4*)&S[w * 256 + p * 128 + 4 * lane] = pr;
            *(float4*)&arow[p * 128 + 4 * lane] = pr;
        }
    }

    // ---- Phase D: ctx = P @ value. Warp w -> krows {(w&1)*2, +1}, vd half w>>1.
    const int kp2 = (w & 1) * 2;
    const int vh  = (w >> 1) * 64;
    float2 c0 = make_float2(0.f, 0.f);
    float2 c1 = make_float2(0.f, 0.f);
    const float* val_b = value + (size_t)b * LQ * VD;
    for (int qt = 0; qt < 8; qt++) {
        __syncthreads();             // prior round reads (and C's S writes) done
        #pragma unroll
        for (int j = 0; j < 8; j++) {      // stage 32x128 value tile (1024 float4)
            int idx = t + 128 * j;
            int q = idx >> 5, c4 = idx & 31;
            *(float4*)&val_s[q * VD + c4 * 4] =
                *(const float4*)&val_b[(qt * 32 + q) * VD + c4 * 4];
        }
        __syncthreads();
        #pragma unroll
        for (int q4 = 0; q4 < 8; q4++) {
            float4 P0 = *(const float4*)&S[(kp2)     * 256 + qt * 32 + q4 * 4];
            float4 P1 = *(const float4*)&S[(kp2 + 1) * 256 + qt * 32 + q4 * 4];
            const float pa0[4] = { P0.x, P0.y, P0.z, P0.w };
            const float pa1[4] = { P1.x, P1.y, P1.z, P1.w };
            #pragma unroll
            for (int u = 0; u < 4; u++) {
                float2 vv = *(const float2*)&val_s[(q4 * 4 + u) * VD + vh + 2 * lane];
                c0.x += pa0[u] * vv.x; c0.y += pa0[u] * vv.y;
                c1.x += pa1[u] * vv.x; c1.y += pa1[u] * vv.y;
            }
        }
    }
    *(float2*)&ctx[(size_t)(b * LK + k0 + kp2)     * VD + vh + 2 * lane] = c0;
    *(float2*)&ctx[(size_t)(b * LK + k0 + kp2 + 1) * VD + vh + 2 * lane] = c1;
}

// ============================================================================
// Launch: inputs: query, key, value, Wq, Wk, v
// d_out = context [B,LK,VD] followed by attention [B,LK,LQ]
// ============================================================================
extern "C" void kernel_launch(void* const* d_in, const int* in_sizes, int n_in,
                              void* d_out, int out_size)
{
    const float* query = (const float*)d_in[0];
    const float* key_t = (const float*)d_in[1];
    const float* value = (const float*)d_in[2];
    const float* Wq    = (const float*)d_in[3];
    const float* Wk    = (const float*)d_in[4];
    const float* vvec  = (const float*)d_in[5];

    float* ctx  = (float*)d_out;
    float* attn = ctx + (size_t)B_ * LK * VD;

    dim3 g1((B_ * LQ) / 32, 2);          // 256 CTAs
    proj_kernel<<<g1, 256>>>(query, key_t, Wq, Wk);
    attn_kernel<<<B_ * (LK / KT), 128>>>(value, vvec, ctx, attn);
}

// round 11
// speedup vs baseline: 1.3440x; 1.0575x over previous
#include <cuda_runtime.h>
#include <cuda_fp16.h>
#include <cuda_bf16.h>

#define B_  16
#define LQ  256
#define LK  256
#define QD  256
#define HD  128
#define VD  128
#define KT  4     // k-rows per CTA; EVERY warp computes all 4, warp w owns q-strip w

// f16 projected q/k, TRANSPOSED per batch: [b][h][q] / [b][h][k]
__device__ __half g_qpT[B_ * HD * LQ];
__device__ __half g_kpT[B_ * HD * LK];

namespace {  // internal linkage: immune to cuda_fp16.hpp name collisions

__device__ __forceinline__ __half2 tanh_h2_(__half2 x) {
    unsigned xo, xi = *(unsigned*)&x;
    asm("tanh.approx.f16x2 %0, %1;" : "=r"(xo) : "r"(xi));
    return *(__half2*)&xo;
}
__device__ __forceinline__ unsigned long long pk2_(float lo, float hi) {
    unsigned long long r;
    asm("mov.b64 %0, {%1, %2};" : "=l"(r) : "f"(lo), "f"(hi));
    return r;
}
__device__ __forceinline__ void upk2_(unsigned long long v, float& lo, float& hi) {
    asm("mov.b64 {%0, %1}, %2;" : "=f"(lo), "=f"(hi) : "l"(v));
}
__device__ __forceinline__ void fma2_(unsigned long long& d, unsigned long long a,
                                      unsigned long long b) {
    asm("fma.rn.f32x2 %0, %1, %2, %0;" : "+l"(d) : "l"(a), "l"(b));
}

}  // namespace

// ============================================================================
// Kernel 1: qp = query @ Wq, kp = key @ Wk  (fp32 math, f32x2 FFMA, epilogue
// stores f16 TRANSPOSED [b][h][row]). BM=32, BN=128, BK=32, 256 threads.
// ============================================================================
__global__ __launch_bounds__(256) void proj_kernel(
    const float* __restrict__ q_in, const float* __restrict__ k_in,
    const float* __restrict__ Wq,   const float* __restrict__ Wk)
{
    const float* X  = blockIdx.y ? k_in : q_in;
    const float* W  = blockIdx.y ? Wk : Wq;
    __half*      YT = blockIdx.y ? g_kpT : g_qpT;

    __shared__ __align__(16) float As[32][36];
    __shared__ __align__(16) float Bs[32][128];

    const int t  = threadIdx.x;
    const int tx = t & 31;
    const int ty = t >> 5;
    const int r0 = blockIdx.x * 32;

    unsigned long long acc[2][4];
    #pragma unroll
    for (int rp = 0; rp < 2; rp++)
        #pragma unroll
        for (int c = 0; c < 4; c++) acc[rp][c] = 0ull;

    for (int kb = 0; kb < QD; kb += 32) {
        __syncthreads();
        {   // A tile 32x32 transposed
            int kk4 = t & 7, r = t >> 3;
            float4 a4 = *(const float4*)&X[(r0 + r) * QD + kb + kk4 * 4];
            As[kk4 * 4 + 0][r] = a4.x;
            As[kk4 * 4 + 1][r] = a4.y;
            As[kk4 * 4 + 2][r] = a4.z;
            As[kk4 * 4 + 3][r] = a4.w;
        }
        {   // B tile 32x128
            int h4 = t & 31, kk = t >> 5;
            #pragma unroll
            for (int j = 0; j < 4; j++)
                *(float4*)&Bs[kk + 8 * j][h4 * 4] =
                    *(const float4*)&W[(kb + kk + 8 * j) * HD + h4 * 4];
        }
        __syncthreads();
        #pragma unroll
        for (int kk = 0; kk < 32; kk++) {
            float4 a  = *(const float4*)&As[kk][ty * 4];
            float4 bv = *(const float4*)&Bs[kk][tx * 4];
            unsigned long long ap0 = pk2_(a.x, a.y);
            unsigned long long ap1 = pk2_(a.z, a.w);
            unsigned long long bb[4] = { pk2_(bv.x, bv.x), pk2_(bv.y, bv.y),
                                         pk2_(bv.z, bv.z), pk2_(bv.w, bv.w) };
            #pragma unroll
            for (int c = 0; c < 4; c++) { fma2_(acc[0][c], ap0, bb[c]);
                                          fma2_(acc[1][c], ap1, bb[c]); }
        }
    }

    const int bb   = r0 / LQ;
    const int qloc = (r0 % LQ) + ty * 4;
    #pragma unroll
    for (int c = 0; c < 4; c++) {
        int h = tx * 4 + c;
        float r01lo, r01hi, r23lo, r23hi;
        upk2_(acc[0][c], r01lo, r01hi);
        upk2_(acc[1][c], r23lo, r23hi);
        __half2 p0 = __floats2half2_rn(r01lo, r01hi);
        __half2 p1 = __floats2half2_rn(r23lo, r23hi);
        uint2 out = make_uint2(*(unsigned*)&p0, *(unsigned*)&p1);
        *(uint2*)&YT[(bb * HD + h) * LQ + qloc] = out;
    }
}

// ============================================================================
// Kernel 2: scores (f16x2 MUFU) + softmax + context.
// grid = B*(LK/4) = 1024 CTAs, 128 threads (4 warps), launch_bounds(128,8).
// Phase B: warp w owns q-strip [64w, 64w+64), lane = 2 q; computes ALL 4 k-rows.
//   Per h: LDS.32 qp + LDS.128 bcast {4 kp dups} + LDS.32 bcast v = 3 wf
//   -> 4 HADD2 + 4 tanh.f16x2 + 4 HFMA2 = 8 tanh. MUFU-bound by design.
//   h in 4 chunks of 32; 8 f16 chains (even/odd), f32 flush every 8 h.
// Phase C: scores -> smem, warp w reduces k-row w (softmax over 256 q).
// Phase D: warp = (k-pair, vd-half); value tiles 32x128 staged in smem.
// smem union (20.5KB): [qps 32hx128u (16K) | kvs 32 uint4 | vvs 32u]
//                  <-> [S 4x256 f32 (4K) | val_s 32x128 f32 (16K)]
// ============================================================================
__global__ __launch_bounds__(128, 8) void attn_kernel(
    const float* __restrict__ value, const float* __restrict__ vvec,
    float* __restrict__ ctx, float* __restrict__ attn)
{
    const int b  = blockIdx.x >> 6;          // 64 k-tiles per batch
    const int k0 = (blockIdx.x & 63) * KT;

    __shared__ __align__(16) float sm[5120];             // 20480 B union
    unsigned* qps  = (unsigned*)sm;                       // [32][128] half2 (16384 B)
    uint4*    kvs4 = (uint4*)((char*)sm + 16384);         // [32] 4x kp dup  (512 B)
    unsigned* vvs  = (unsigned*)((char*)sm + 16896);      // [32] v dup      (128 B)
    float*    S     = sm;                                 // [4][256]        (4096 B)
    float*    val_s = sm + 1024;                          // [32][128]       (16384 B)

    const int t    = threadIdx.x;
    const int w    = t >> 5;
    const int lane = t & 31;
    const int qidx = w * 32 + lane;          // uint index; q = 2*qidx, 2*qidx+1

    const __half* kpT = g_kpT + (size_t)b * HD * LK;
    const __half* qpT = g_qpT + (size_t)b * HD * LQ;

    float accf[4][2];                        // [k][2 q]
    #pragma unroll
    for (int k = 0; k < 4; k++) { accf[k][0] = 0.f; accf[k][1] = 0.f; }

    // ---- Phase B: scores, h in 4 chunks of 32 ----
    #pragma unroll
    for (int hc = 0; hc < HD; hc += 32) {
        __syncthreads();                     // prior chunk readers done
        if (t < 32) {                        // kvs4[h] = 4x dup kp, vvs[h] = dup v
            int h = t;
            uint2 kk = *(const uint2*)&kpT[(hc + h) * LK + k0];
            __half2 kp01 = *(__half2*)&kk.x;
            __half2 kp23 = *(__half2*)&kk.y;
            __half2 d0 = __low2half2(kp01), d1 = __high2half2(kp01);
            __half2 d2 = __low2half2(kp23), d3 = __high2half2(kp23);
            kvs4[h] = make_uint4(*(unsigned*)&d0, *(unsigned*)&d1,
                                 *(unsigned*)&d2, *(unsigned*)&d3);
            __half2 vd = __float2half2_rn(vvec[hc + h]);
            vvs[h] = *(unsigned*)&vd;
        }
        {   // qps: 32h x 256q = 1024 uint4, 8 per thread
            #pragma unroll
            for (int j = 0; j < 8; j++) {
                int idx = t + 128 * j;
                int h = idx >> 5, u4 = idx & 31;
                ((uint4*)qps)[h * 32 + u4] =
                    *(const uint4*)&qpT[(hc + h) * LQ + u4 * 8];
            }
        }
        __syncthreads();
        #pragma unroll
        for (int h8 = 0; h8 < 32; h8 += 8) {
            __half2 ae[4], ao[4];
            #pragma unroll
            for (int k = 0; k < 4; k++) { ae[k] = __float2half2_rn(0.f); ao[k] = ae[k]; }
            #pragma unroll
            for (int j = 0; j < 8; j++) {
                int h = h8 + j;
                unsigned qu = qps[h * 128 + qidx];       // lane-strided, 1 wf
                uint4 kv = kvs4[h];                      // bcast, 1 wf
                unsigned vu = vvs[h];                    // bcast, 1 wf
                __half2 qv = *(__half2*)&qu;
                __half2 vd = *(__half2*)&vu;
                __half2 t0 = tanh_h2_(__hadd2(qv, *(__half2*)&kv.x));
                __half2 t1 = tanh_h2_(__hadd2(qv, *(__half2*)&kv.y));
                __half2 t2 = tanh_h2_(__hadd2(qv, *(__half2*)&kv.z));
                __half2 t3 = tanh_h2_(__hadd2(qv, *(__half2*)&kv.w));
                if (j & 1) {
                    ao[0] = __hfma2(t0, vd, ao[0]); ao[1] = __hfma2(t1, vd, ao[1]);
                    ao[2] = __hfma2(t2, vd, ao[2]); ao[3] = __hfma2(t3, vd, ao[3]);
                } else {
                    ae[0] = __hfma2(t0, vd, ae[0]); ae[1] = __hfma2(t1, vd, ae[1]);
                    ae[2] = __hfma2(t2, vd, ae[2]); ae[3] = __hfma2(t3, vd, ae[3]);
                }
            }
            #pragma unroll
            for (int k = 0; k < 4; k++) {
                float2 f2 = __half22float2(__hadd2(ae[k], ao[k]));
                accf[k][0] += f2.x;
                accf[k][1] += f2.y;
            }
        }
    }

    // ---- Phase C: softmax over q (scores -> S, warp w reduces k-row w) ----
    __syncthreads();                         // phase-B smem reads done before S overlay
    #pragma unroll
    for (int k = 0; k < 4; k++)
        *(float2*)&S[k * 256 + 2 * qidx] = make_float2(accf[k][0], accf[k][1]);
    __syncthreads();
    {
        float vals[8], m = -1e30f;
        #pragma unroll
        for (int i = 0; i < 8; i++) {
            vals[i] = S[w * 256 + lane + 32 * i];
            m = fmaxf(m, vals[i]);
        }
        #pragma unroll
        for (int o = 16; o > 0; o >>= 1)
            m = fmaxf(m, __shfl_xor_sync(0xffffffffu, m, o));
        float s = 0.f;
        #pragma unroll
        for (int i = 0; i < 8; i++) { vals[i] = __expf(vals[i] - m); s += vals[i]; }
        #pragma unroll
        for (int o = 16; o > 0; o >>= 1)
            s += __shfl_xor_sync(0xffffffffu, s, o);
        float inv = 1.0f / s;
        #pragma unroll
        for (int i = 0; i < 8; i++)
            S[w * 256 + lane + 32 * i] = vals[i] * inv;
        __syncwarp();
        float* arow = attn + (size_t)(b * LK + k0 + w) * LQ;
        #pragma unroll
        for (int j = 0; j < 2; j++)
            *(float4*)&arow[lane * 4 + 128 * j] =
                *(const float4*)&S[w * 256 + lane * 4 + 128 * j];
    }

    // ---- Phase D: ctx = P @ value. Warp w -> krows {(w&1)*2,+1}, vd half w>>1.
    const int kp2 = (w & 1) * 2;
    const int vh  = (w >> 1) * 64;
    float2 c0 = make_float2(0.f, 0.f);
    float2 c1 = make_float2(0.f, 0.f);
    const float* val_b = value + (size_t)b * LQ * VD;
    for (int qt = 0; qt < 8; qt++) {
        __syncthreads();                     // P writes / prior tile reads done
        #pragma unroll
        for (int j = 0; j < 8; j++) {        // stage 32x128 value tile (1024 float4)
            int idx = t + 128 * j;
            int q = idx >> 5, c4 = idx & 31;
            *(float4*)&val_s[q * VD + c4 * 4] =
                *(const float4*)&val_b[(qt * 32 + q) * VD + c4 * 4];
        }
        __syncthreads();
        #pragma unroll
        for (int q4 = 0; q4 < 8; q4++) {
            float4 P0 = *(const float4*)&S[(kp2)     * 256 + qt * 32 + q4 * 4];
            float4 P1 = *(const float4*)&S[(kp2 + 1) * 256 + qt * 32 + q4 * 4];
            const float pa0[4] = { P0.x, P0.y, P0.z, P0.w };
            const float pa1[4] = { P1.x, P1.y, P1.z, P1.w };
            #pragma unroll
            for (int u = 0; u < 4; u++) {
                float2 vv = *(const float2*)&val_s[(q4 * 4 + u) * VD + vh + 2 * lane];
                c0.x += pa0[u] * vv.x; c0.y += pa0[u] * vv.y;
                c1.x += pa1[u] * vv.x; c1.y += pa1[u] * vv.y;
            }
        }
    }
    *(float2*)&ctx[(size_t)(b * LK + k0 + kp2)     * VD + vh + 2 * lane] = c0;
    *(float2*)&ctx[(size_t)(b * LK + k0 + kp2 + 1) * VD + vh + 2 * lane] = c1;
}

// ============================================================================
// Launch: inputs: query, key, value, Wq, Wk, v
// d_out = context [B,LK,VD] followed by attention [B,LK,LQ]
// ============================================================================
extern "C" void kernel_launch(void* const* d_in, const int* in_sizes, int n_in,
                              void* d_out, int out_size)
{
    const float* query = (const float*)d_in[0];
    const float* key_t = (const float*)d_in[1];
    const float* value = (const float*)d_in[2];
    const float* Wq    = (const float*)d_in[3];
    const float* Wk    = (const float*)d_in[4];
    const float* vvec  = (const float*)d_in[5];

    float* ctx  = (float*)d_out;
    float* attn = ctx + (size_t)B_ * LK * VD;

    dim3 g1((B_ * LQ) / 32, 2);          // 256 CTAs
    proj_kernel<<<g1, 256>>>(query, key_t, Wq, Wk);
    attn_kernel<<<B_ * (LK / KT), 128>>>(value, vvec, ctx, attn);
}

// round 12
// speedup vs baseline: 1.4782x; 1.0998x over previous
#include <cuda_runtime.h>
#include <cuda_fp16.h>
#include <cuda_bf16.h>

#define B_  16
#define LQ  256
#define LK  256
#define QD  256
#define HD  128
#define VD  128
#define KT  4     // k-rows per CTA; every warp computes all 4 for its 64-q strip

// f16 projected q/k, TRANSPOSED per batch: [b][h][q] / [b][h][k]  (2MB: L2-resident)
__device__ __half g_qpT[B_ * HD * LQ];
__device__ __half g_kpT[B_ * HD * LK];

namespace {  // internal linkage: immune to cuda_fp16.hpp name collisions

__device__ __forceinline__ __half2 tanh_h2_(__half2 x) {
    unsigned xo, xi = *(unsigned*)&x;
    asm("tanh.approx.f16x2 %0, %1;" : "=r"(xo) : "r"(xi));
    return *(__half2*)&xo;
}
__device__ __forceinline__ unsigned long long pk2_(float lo, float hi) {
    unsigned long long r;
    asm("mov.b64 %0, {%1, %2};" : "=l"(r) : "f"(lo), "f"(hi));
    return r;
}
__device__ __forceinline__ void upk2_(unsigned long long v, float& lo, float& hi) {
    asm("mov.b64 {%0, %1}, %2;" : "=f"(lo), "=f"(hi) : "l"(v));
}
__device__ __forceinline__ void fma2_(unsigned long long& d, unsigned long long a,
                                      unsigned long long b) {
    asm("fma.rn.f32x2 %0, %1, %2, %0;" : "+l"(d) : "l"(a), "l"(b));
}

}  // namespace

// ============================================================================
// Kernel 1: qp = query @ Wq, kp = key @ Wk  (fp32 math, f32x2 FFMA, epilogue
// stores f16 TRANSPOSED [b][h][row]). BM=32, BN=128, BK=32, 256 threads.
// ============================================================================
__global__ __launch_bounds__(256) void proj_kernel(
    const float* __restrict__ q_in, const float* __restrict__ k_in,
    const float* __restrict__ Wq,   const float* __restrict__ Wk)
{
    const float* X  = blockIdx.y ? k_in : q_in;
    const float* W  = blockIdx.y ? Wk : Wq;
    __half*      YT = blockIdx.y ? g_kpT : g_qpT;

    __shared__ __align__(16) float As[32][36];
    __shared__ __align__(16) float Bs[32][128];

    const int t  = threadIdx.x;
    const int tx = t & 31;
    const int ty = t >> 5;
    const int r0 = blockIdx.x * 32;

    unsigned long long acc[2][4];
    #pragma unroll
    for (int rp = 0; rp < 2; rp++)
        #pragma unroll
        for (int c = 0; c < 4; c++) acc[rp][c] = 0ull;

    for (int kb = 0; kb < QD; kb += 32) {
        __syncthreads();
        {   // A tile 32x32 transposed
            int kk4 = t & 7, r = t >> 3;
            float4 a4 = *(const float4*)&X[(r0 + r) * QD + kb + kk4 * 4];
            As[kk4 * 4 + 0][r] = a4.x;
            As[kk4 * 4 + 1][r] = a4.y;
            As[kk4 * 4 + 2][r] = a4.z;
            As[kk4 * 4 + 3][r] = a4.w;
        }
        {   // B tile 32x128
            int h4 = t & 31, kk = t >> 5;
            #pragma unroll
            for (int j = 0; j < 4; j++)
                *(float4*)&Bs[kk + 8 * j][h4 * 4] =
                    *(const float4*)&W[(kb + kk + 8 * j) * HD + h4 * 4];
        }
        __syncthreads();
        #pragma unroll
        for (int kk = 0; kk < 32; kk++) {
            float4 a  = *(const float4*)&As[kk][ty * 4];
            float4 bv = *(const float4*)&Bs[kk][tx * 4];
            unsigned long long ap0 = pk2_(a.x, a.y);
            unsigned long long ap1 = pk2_(a.z, a.w);
            unsigned long long bb[4] = { pk2_(bv.x, bv.x), pk2_(bv.y, bv.y),
                                         pk2_(bv.z, bv.z), pk2_(bv.w, bv.w) };
            #pragma unroll
            for (int c = 0; c < 4; c++) { fma2_(acc[0][c], ap0, bb[c]);
                                          fma2_(acc[1][c], ap1, bb[c]); }
        }
    }

    const int bb   = r0 / LQ;
    const int qloc = (r0 % LQ) + ty * 4;
    #pragma unroll
    for (int c = 0; c < 4; c++) {
        int h = tx * 4 + c;
        float r01lo, r01hi, r23lo, r23hi;
        upk2_(acc[0][c], r01lo, r01hi);
        upk2_(acc[1][c], r23lo, r23hi);
        __half2 p0 = __floats2half2_rn(r01lo, r01hi);
        __half2 p1 = __floats2half2_rn(r23lo, r23hi);
        uint2 out = make_uint2(*(unsigned*)&p0, *(unsigned*)&p1);
        *(uint2*)&YT[(bb * HD + h) * LQ + qloc] = out;
    }
}

// ============================================================================
// Kernel 2: scores + softmax + context. grid = 1024 CTAs, 128 threads.
// Phase B: NO SMEM, NO BARRIERS. Warp w owns q-strip [64w,64w+64), lane=2 q.
//   Per h: LDG.32 qp (coalesced, L2) + LDG.64 kp (uniform) + LDG.32 v (uniform)
//   -> 4 HADD2 (kp dup via half-lane select) + 4 tanh.f16x2 + 4 HFMA2 = 8 tanh.
//   Unroll 8 h (24 loads in flight); f16 chains flushed to f32 every 8 h.
// Phase C: scores -> S smem, barrier, warp w softmaxes k-row w.
// Phase D: value tiles converted to f16 at staging (halves crossbar traffic);
//   warp = (k-pair, vd-half). smem total 12.2KB -> launch_bounds(128,8).
// ============================================================================
__global__ __launch_bounds__(128, 8) void attn_kernel(
    const float* __restrict__ value, const float* __restrict__ vvec,
    float* __restrict__ ctx, float* __restrict__ attn)
{
    const int b  = blockIdx.x >> 6;          // 64 k-tiles per batch
    const int k0 = (blockIdx.x & 63) * KT;

    __shared__ __align__(16) float    S[4 * 256];        // 4096 B
    __shared__ __align__(16) unsigned val16[32 * 64];    // 8192 B (f16x2 value tile)

    const int t    = threadIdx.x;
    const int w    = t >> 5;
    const int lane = t & 31;
    const int qidx = w * 32 + lane;          // q = 2*qidx, 2*qidx+1

    const __half* qb = g_qpT + (size_t)b * HD * LQ + 2 * qidx;
    const __half* kb = g_kpT + (size_t)b * HD * LK + k0;

    float accf[4][2];
    #pragma unroll
    for (int k = 0; k < 4; k++) { accf[k][0] = 0.f; accf[k][1] = 0.f; }

    // ---- Phase B: scores, straight from gmem (L2-resident) ----
    #pragma unroll 2
    for (int h8 = 0; h8 < HD; h8 += 8) {
        unsigned qv[8]; uint2 kp[8]; float vf[8];
        #pragma unroll
        for (int j = 0; j < 8; j++) {
            qv[j] = *(const unsigned*)(qb + (h8 + j) * LQ);   // lane-strided
            kp[j] = *(const uint2*)  (kb + (h8 + j) * LK);    // uniform
            vf[j] = vvec[h8 + j];                             // uniform
        }
        __half2 ae[4], ao[4];
        #pragma unroll
        for (int k = 0; k < 4; k++) { ae[k] = __float2half2_rn(0.f); ao[k] = ae[k]; }
        #pragma unroll
        for (int j = 0; j < 8; j++) {
            __half2 q2   = *(__half2*)&qv[j];
            __half2 kp01 = *(__half2*)&kp[j].x;
            __half2 kp23 = *(__half2*)&kp[j].y;
            __half2 vd   = __float2half2_rn(vf[j]);
            __half2 t0 = tanh_h2_(__hadd2(q2, __low2half2(kp01)));
            __half2 t1 = tanh_h2_(__hadd2(q2, __high2half2(kp01)));
            __half2 t2 = tanh_h2_(__hadd2(q2, __low2half2(kp23)));
            __half2 t3 = tanh_h2_(__hadd2(q2, __high2half2(kp23)));
            if (j & 1) {
                ao[0] = __hfma2(t0, vd, ao[0]); ao[1] = __hfma2(t1, vd, ao[1]);
                ao[2] = __hfma2(t2, vd, ao[2]); ao[3] = __hfma2(t3, vd, ao[3]);
            } else {
                ae[0] = __hfma2(t0, vd, ae[0]); ae[1] = __hfma2(t1, vd, ae[1]);
                ae[2] = __hfma2(t2, vd, ae[2]); ae[3] = __hfma2(t3, vd, ae[3]);
            }
        }
        #pragma unroll
        for (int k = 0; k < 4; k++) {
            float2 f2 = __half22float2(__hadd2(ae[k], ao[k]));
            accf[k][0] += f2.x;
            accf[k][1] += f2.y;
        }
    }

    // ---- Phase C: softmax over q (scores -> S, warp w reduces k-row w) ----
    #pragma unroll
    for (int k = 0; k < 4; k++)
        *(float2*)&S[k * 256 + 2 * qidx] = make_float2(accf[k][0], accf[k][1]);
    __syncthreads();
    {
        float vals[8], m = -1e30f;
        #pragma unroll
        for (int i = 0; i < 8; i++) {
            vals[i] = S[w * 256 + lane + 32 * i];
            m = fmaxf(m, vals[i]);
        }
        #pragma unroll
        for (int o = 16; o > 0; o >>= 1)
            m = fmaxf(m, __shfl_xor_sync(0xffffffffu, m, o));
        float s = 0.f;
        #pragma unroll
        for (int i = 0; i < 8; i++) { vals[i] = __expf(vals[i] - m); s += vals[i]; }
        #pragma unroll
        for (int o = 16; o > 0; o >>= 1)
            s += __shfl_xor_sync(0xffffffffu, s, o);
        float inv = 1.0f / s;
        #pragma unroll
        for (int i = 0; i < 8; i++)
            S[w * 256 + lane + 32 * i] = vals[i] * inv;
        __syncwarp();
        float* arow = attn + (size_t)(b * LK + k0 + w) * LQ;
        #pragma unroll
        for (int j = 0; j < 2; j++)
            *(float4*)&arow[lane * 4 + 128 * j] =
                *(const float4*)&S[w * 256 + lane * 4 + 128 * j];
    }

    // ---- Phase D: ctx = P @ value (value f16 in smem). ----
    // Warp w -> k-rows {(w&1)*2, +1}, vd half (w>>1): uint offset 32*(w>>1)+lane.
    const int kp2  = (w & 1) * 2;
    const int voff = (w >> 1) * 32;
    float2 c0 = make_float2(0.f, 0.f);
    float2 c1 = make_float2(0.f, 0.f);
    const float* val_b = value + (size_t)b * LQ * VD;
    for (int qt = 0; qt < 8; qt++) {
        __syncthreads();                     // S/softmax writes + prior tile reads done
        #pragma unroll
        for (int j = 0; j < 8; j++) {        // stage 32x128 value tile as f16
            int idx = t + 128 * j;           // 1024 float4 slots
            int q = idx >> 5, c4 = idx & 31;
            float4 v4 = *(const float4*)&val_b[(qt * 32 + q) * VD + c4 * 4];
            __half2 h0 = __floats2half2_rn(v4.x, v4.y);
            __half2 h1 = __floats2half2_rn(v4.z, v4.w);
            *(uint2*)&val16[q * 64 + c4 * 2] =
                make_uint2(*(unsigned*)&h0, *(unsigned*)&h1);
        }
        __syncthreads();
        #pragma unroll
        for (int q4 = 0; q4 < 8; q4++) {
            float4 P0 = *(const float4*)&S[(kp2)     * 256 + qt * 32 + q4 * 4];
            float4 P1 = *(const float4*)&S[(kp2 + 1) * 256 + qt * 32 + q4 * 4];
            const float pa0[4] = { P0.x, P0.y, P0.z, P0.w };
            const float pa1[4] = { P1.x, P1.y, P1.z, P1.w };
            #pragma unroll
            for (int u = 0; u < 4; u++) {
                unsigned hv = val16[(q4 * 4 + u) * 64 + voff + lane];
                float2 f = __half22float2(*(__half2*)&hv);
                c0.x += pa0[u] * f.x; c0.y += pa0[u] * f.y;
                c1.x += pa1[u] * f.x; c1.y += pa1[u] * f.y;
            }
        }
    }
    const int vh = voff * 2;
    *(float2*)&ctx[(size_t)(b * LK + k0 + kp2)     * VD + vh + 2 * lane] = c0;
    *(float2*)&ctx[(size_t)(b * LK + k0 + kp2 + 1) * VD + vh + 2 * lane] = c1;
}

// ============================================================================
// Launch: inputs: query, key, value, Wq, Wk, v
// d_out = context [B,LK,VD] followed by attention [B,LK,LQ]
// ============================================================================
extern "C" void kernel_launch(void* const* d_in, const int* in_sizes, int n_in,
                              void* d_out, int out_size)
{
    const float* query = (const float*)d_in[0];
    const float* key_t = (const float*)d_in[1];
    const float* value = (const float*)d_in[2];
    const float* Wq    = (const float*)d_in[3];
    const float* Wk    = (const float*)d_in[4];
    const float* vvec  = (const float*)d_in[5];

    float* ctx  = (float*)d_out;
    float* attn = ctx + (size_t)B_ * LK * VD;

    dim3 g1((B_ * LQ) / 32, 2);          // 256 CTAs
    proj_kernel<<<g1, 256>>>(query, key_t, Wq, Wk);
    attn_kernel<<<B_ * (LK / KT), 128>>>(value, vvec, ctx, attn);
}